// round 2
// baseline (speedup 1.0000x reference)
#include <cuda_runtime.h>
#include <math.h>

#define S_DIM 256
#define T_DIM 64
#define B_DIM 8
#define H_DIM 768
#define V_DIM 50257

// ---------------- device scratch (no allocs allowed) ----------------
__device__ float g_dec_proj[T_DIM * B_DIM * H_DIM];   // (T,B,H)
__device__ float g_enc_proj[S_DIM * B_DIM * H_DIM];   // (S,B,H)
__device__ float g_attn[T_DIM * B_DIM * S_DIM];       // (T,B,S) scores -> probs in place
__device__ float g_ctx[T_DIM * B_DIM * H_DIM];        // (T,B,H)
__device__ float g_pg[T_DIM * B_DIM];                 // p_gen per (t,b)

__device__ __forceinline__ float tanh_fast(float x) {
    float y;
    asm("tanh.approx.f32 %0, %1;" : "=f"(y) : "f"(x));
    return y;
}

// ---------------- generic SGEMM: C[M,N] = A[M,K] @ B[K,N] (+bias) ----------------
// BM=BN=128, BK=8, 256 threads, 8x8 per thread. M % 128 == 0, K % 8 == 0 assumed.
__global__ __launch_bounds__(256) void sgemm128(
    const float* __restrict__ A, const float* __restrict__ Bm,
    const float* __restrict__ bias, float* __restrict__ C,
    int M, int N, int K)
{
    const int BM = 128, BN = 128, BK = 8;
    __shared__ __align__(16) float As[BK][BM];
    __shared__ __align__(16) float Bs[BK][BN];

    int tid = threadIdx.x;
    int tx = tid & 15;        // 0..15 -> N sub-tile
    int ty = tid >> 4;        // 0..15 -> M sub-tile
    int aRow = tid >> 1;      // 0..127
    int aCol = (tid & 1) * 4; // 0 or 4
    int bRow = tid >> 5;      // 0..7
    int bColBase = (tid & 31) * 4;

    int mBase = blockIdx.y * BM;
    int nBase = blockIdx.x * BN;

    float acc[8][8];
#pragma unroll
    for (int i = 0; i < 8; i++)
#pragma unroll
        for (int j = 0; j < 8; j++) acc[i][j] = 0.f;

    for (int k0 = 0; k0 < K; k0 += BK) {
        float4 av = *reinterpret_cast<const float4*>(&A[(size_t)(mBase + aRow) * K + k0 + aCol]);
        As[aCol + 0][aRow] = av.x;
        As[aCol + 1][aRow] = av.y;
        As[aCol + 2][aRow] = av.z;
        As[aCol + 3][aRow] = av.w;

        const float* brow = &Bm[(size_t)(k0 + bRow) * N];
#pragma unroll
        for (int j = 0; j < 4; j++) {
            int c = nBase + bColBase + j;
            Bs[bRow][bColBase + j] = (c < N) ? brow[c] : 0.f;
        }
        __syncthreads();

#pragma unroll
        for (int k = 0; k < BK; k++) {
            float4 a0 = *reinterpret_cast<const float4*>(&As[k][ty * 8]);
            float4 a1 = *reinterpret_cast<const float4*>(&As[k][ty * 8 + 4]);
            float4 b0 = *reinterpret_cast<const float4*>(&Bs[k][tx * 8]);
            float4 b1 = *reinterpret_cast<const float4*>(&Bs[k][tx * 8 + 4]);
            float af[8] = {a0.x, a0.y, a0.z, a0.w, a1.x, a1.y, a1.z, a1.w};
            float bf[8] = {b0.x, b0.y, b0.z, b0.w, b1.x, b1.y, b1.z, b1.w};
#pragma unroll
            for (int i = 0; i < 8; i++)
#pragma unroll
                for (int j = 0; j < 8; j++)
                    acc[i][j] = fmaf(af[i], bf[j], acc[i][j]);
        }
        __syncthreads();
    }

#pragma unroll
    for (int i = 0; i < 8; i++) {
        size_t r = (size_t)(mBase + ty * 8 + i);
#pragma unroll
        for (int j = 0; j < 8; j++) {
            int c = nBase + tx * 8 + j;
            if (c < N) C[r * N + c] = acc[i][j] + (bias ? bias[c] : 0.f);
        }
    }
}

// ---------------- attention scores: attn[t,b,s] = sum_h tanh(dec+enc)*v ----------------
// grid = B * (T/2), 256 threads (8 warps). Warp: t = pair*2 + (w&1), s-chunk = (w>>1)*64.
__global__ __launch_bounds__(256) void attn_score_kernel(const float* __restrict__ v_attn)
{
    int b = blockIdx.x >> 5;   // T/2 = 32 pairs
    int tp = blockIdx.x & 31;
    int w = threadIdx.x >> 5;
    int lane = threadIdx.x & 31;
    int t = tp * 2 + (w & 1);
    int sc = w >> 1;           // 0..3

    const float* drow = g_dec_proj + (size_t)(t * B_DIM + b) * H_DIM;
    float4 dreg[6], vreg[6];
#pragma unroll
    for (int i = 0; i < 6; i++) {
        dreg[i] = *reinterpret_cast<const float4*>(drow + i * 128 + lane * 4);
        vreg[i] = *reinterpret_cast<const float4*>(v_attn + i * 128 + lane * 4);
    }

    for (int s = sc * 64; s < sc * 64 + 64; s++) {
        const float* erow = g_enc_proj + (size_t)(s * B_DIM + b) * H_DIM;
        float acc = 0.f;
#pragma unroll
        for (int i = 0; i < 6; i++) {
            float4 e = *reinterpret_cast<const float4*>(erow + i * 128 + lane * 4);
            acc = fmaf(tanh_fast(dreg[i].x + e.x), vreg[i].x, acc);
            acc = fmaf(tanh_fast(dreg[i].y + e.y), vreg[i].y, acc);
            acc = fmaf(tanh_fast(dreg[i].z + e.z), vreg[i].z, acc);
            acc = fmaf(tanh_fast(dreg[i].w + e.w), vreg[i].w, acc);
        }
#pragma unroll
        for (int off = 16; off > 0; off >>= 1)
            acc += __shfl_xor_sync(0xffffffffu, acc, off);
        if (lane == 0)
            g_attn[(size_t)(t * B_DIM + b) * S_DIM + s] = acc;
    }
}

// ---------------- masked softmax over S (in place on g_attn) ----------------
__global__ __launch_bounds__(256) void softmax_s_kernel(const int* __restrict__ src_ids)
{
    int row = blockIdx.x;          // t*B + b
    int b = row & (B_DIM - 1);
    int s = threadIdx.x;
    float val = g_attn[(size_t)row * S_DIM + s];
    if (src_ids[s * B_DIM + b] == 0) val = -1e10f;

    __shared__ float red[256];
    red[s] = val;
    __syncthreads();
    for (int off = 128; off > 0; off >>= 1) {
        if (s < off) red[s] = fmaxf(red[s], red[s + off]);
        __syncthreads();
    }
    float m = red[0];
    __syncthreads();
    float e = __expf(val - m);
    red[s] = e;
    __syncthreads();
    for (int off = 128; off > 0; off >>= 1) {
        if (s < off) red[s] += red[s + off];
        __syncthreads();
    }
    g_attn[(size_t)row * S_DIM + s] = e / red[0];
}

// ---------------- ctx[t,b,h] = sum_s attn[t,b,s] * encoder_out[s,b,h] ----------------
// grid = B * (T/4), 256 threads, each thread owns h = {tid, tid+256, tid+512}.
__global__ __launch_bounds__(256) void ctx_kernel(const float* __restrict__ enc)
{
    int b = blockIdx.x >> 4;   // T/4 = 16 groups
    int tg = blockIdx.x & 15;
    int tid = threadIdx.x;

    __shared__ float p_sh[4][S_DIM];
    for (int i = tid; i < 4 * S_DIM; i += 256) {
        int tt = i >> 8;
        int ss = i & 255;
        p_sh[tt][ss] = g_attn[(size_t)((tg * 4 + tt) * B_DIM + b) * S_DIM + ss];
    }
    __syncthreads();

    float acc[4][3] = {};
    for (int s = 0; s < S_DIM; s++) {
        const float* erow = enc + (size_t)(s * B_DIM + b) * H_DIM;
        float e0 = erow[tid], e1 = erow[tid + 256], e2 = erow[tid + 512];
#pragma unroll
        for (int tt = 0; tt < 4; tt++) {
            float p = p_sh[tt][s];
            acc[tt][0] = fmaf(p, e0, acc[tt][0]);
            acc[tt][1] = fmaf(p, e1, acc[tt][1]);
            acc[tt][2] = fmaf(p, e2, acc[tt][2]);
        }
    }
#pragma unroll
    for (int tt = 0; tt < 4; tt++) {
        float* crow = g_ctx + (size_t)((tg * 4 + tt) * B_DIM + b) * H_DIM;
        crow[tid] = acc[tt][0];
        crow[tid + 256] = acc[tt][1];
        crow[tid + 512] = acc[tt][2];
    }
}

// ---------------- p_gen = sigmoid([dec;ctx;tgt] . W_pgen + b) ----------------
__global__ __launch_bounds__(256) void pgen_kernel(
    const float* __restrict__ ds, const float* __restrict__ tgt,
    const float* __restrict__ Wp, const float* __restrict__ bp)
{
    int row = blockIdx.x;     // t*B + b
    int tid = threadIdx.x;
    const float* dsr = ds + (size_t)row * H_DIM;
    const float* ctr = g_ctx + (size_t)row * H_DIM;
    const float* tgr = tgt + (size_t)row * H_DIM;
    float part = 0.f;
    for (int h = tid; h < H_DIM; h += 256)
        part += dsr[h] * Wp[h] + ctr[h] * Wp[H_DIM + h] + tgr[h] * Wp[2 * H_DIM + h];

    __shared__ float red[256];
    red[tid] = part;
    __syncthreads();
    for (int off = 128; off > 0; off >>= 1) {
        if (tid < off) red[tid] += red[tid + off];
        __syncthreads();
    }
    if (tid == 0) {
        float x = red[0] + bp[0];
        g_pg[row] = 1.f / (1.f + __expf(-x));
    }
}

// ---------------- softmax over V (in place on d_out), scaled by p_gen ----------------
__global__ __launch_bounds__(1024) void softmax_v_kernel(float* __restrict__ out)
{
    int row = blockIdx.x;     // t*B + b
    float* ptr = out + (size_t)row * V_DIM;
    int tid = threadIdx.x;

    float m = -3.4e38f, sum = 0.f;
    for (int v = tid; v < V_DIM; v += 1024) {
        float x = ptr[v];
        float nm = fmaxf(m, x);
        sum = sum * __expf(m - nm) + __expf(x - nm);
        m = nm;
    }
    __shared__ float sm[1024], ss[1024];
    sm[tid] = m;
    ss[tid] = sum;
    __syncthreads();
    for (int off = 512; off > 0; off >>= 1) {
        if (tid < off) {
            float m2 = sm[tid + off], s2 = ss[tid + off];
            float nm = fmaxf(sm[tid], m2);
            ss[tid] = ss[tid] * __expf(sm[tid] - nm) + s2 * __expf(m2 - nm);
            sm[tid] = nm;
        }
        __syncthreads();
    }
    float M = sm[0];
    float scale = g_pg[row] / ss[0];
    for (int v = tid; v < V_DIM; v += 1024)
        ptr[v] = __expf(ptr[v] - M) * scale;
}

// ---------------- scatter add: out[t,b,src_ids[s,b]] += attn*(1-pg) ----------------
__global__ __launch_bounds__(256) void scatter_kernel(
    const int* __restrict__ src_ids, float* __restrict__ out)
{
    int row = blockIdx.x;     // t*B + b
    int b = row & (B_DIM - 1);
    int s = threadIdx.x;
    float p = g_attn[(size_t)row * S_DIM + s];
    float w = 1.f - g_pg[row];
    int id = src_ids[s * B_DIM + b];
    if (id >= 0 && id < V_DIM)   // defensive: never trap on a bad index
        atomicAdd(out + (size_t)row * V_DIM + (size_t)id, p * w);
}

// ---------------- launcher ----------------
extern "C" void kernel_launch(void* const* d_in, const int* in_sizes, int n_in,
                              void* d_out, int out_size)
{
    const float* enc    = (const float*)d_in[0];   // (S,B,H)
    const float* ds     = (const float*)d_in[1];   // (T,B,H)
    const int*   srcids = (const int*)d_in[2];     // (S,B) — int64 in reference, int32 on device
    const float* tgt    = (const float*)d_in[3];   // (T,B,H)
    const float* W_attn = (const float*)d_in[4];   // (2H,H)
    const float* b_attn = (const float*)d_in[5];   // (H,)
    const float* v_attn = (const float*)d_in[6];   // (H,)
    // d_in[7] = b_v : cancels in softmax (constant shift; masked scores are replaced) -> unused
    const float* W_pgen = (const float*)d_in[8];   // (3H,1)
    const float* b_pgen = (const float*)d_in[9];   // (1,)
    const float* W_gen  = (const float*)d_in[10];  // (H,V)
    const float* b_gen  = (const float*)d_in[11];  // (V,)
    float* out = (float*)d_out;

    float *dec_proj_p, *enc_proj_p;
    cudaGetSymbolAddress((void**)&dec_proj_p, g_dec_proj);
    cudaGetSymbolAddress((void**)&enc_proj_p, g_enc_proj);

    // 1) dec_proj = decoder_state @ W_attn[:H]           (512 x 768, K=768)
    sgemm128<<<dim3(768 / 128, (T_DIM * B_DIM) / 128), 256>>>(
        ds, W_attn, nullptr, dec_proj_p, T_DIM * B_DIM, H_DIM, H_DIM);

    // 2) enc_proj = encoder_out @ W_attn[H:] + b_attn    (2048 x 768, K=768)
    sgemm128<<<dim3(768 / 128, (S_DIM * B_DIM) / 128), 256>>>(
        enc, W_attn + (size_t)H_DIM * H_DIM, b_attn, enc_proj_p,
        S_DIM * B_DIM, H_DIM, H_DIM);

    // 3) additive attention scores
    attn_score_kernel<<<B_DIM * (T_DIM / 2), 256>>>(v_attn);

    // 4) masked softmax over S
    softmax_s_kernel<<<T_DIM * B_DIM, 256>>>(srcids);

    // 5) context vectors
    ctx_kernel<<<B_DIM * (T_DIM / 4), 256>>>(enc);

    // 6) p_gen
    pgen_kernel<<<T_DIM * B_DIM, 256>>>(ds, tgt, W_pgen, b_pgen);

    // 7) vocab logits straight into d_out                (512 x 50257, K=768)
    sgemm128<<<dim3((V_DIM + 127) / 128, (T_DIM * B_DIM) / 128), 256>>>(
        ds, W_gen, b_gen, out, T_DIM * B_DIM, V_DIM, H_DIM);

    // 8) softmax over V, scaled by p_gen (in place)
    softmax_v_kernel<<<T_DIM * B_DIM, 1024>>>(out);

    // 9) scatter-add copy distribution
    scatter_kernel<<<T_DIM * B_DIM, 256>>>(srcids, out);
}

// round 5
// speedup vs baseline: 1.9306x; 1.9306x over previous
#include <cuda_runtime.h>
#include <stdint.h>
#include <math.h>

#define S_DIM 256
#define T_DIM 64
#define B_DIM 8
#define H_DIM 768
#define V_DIM 50257

// ---------------- device scratch (no allocs allowed) ----------------
__device__ float g_dec_proj[T_DIM * B_DIM * H_DIM];   // (T,B,H)
__device__ float g_enc_proj[S_DIM * B_DIM * H_DIM];   // (S,B,H)
__device__ float g_attn[T_DIM * B_DIM * S_DIM];       // (T,B,S) scores -> probs in place
__device__ float g_ctx[T_DIM * B_DIM * H_DIM];        // (T,B,H)
__device__ float g_pg[T_DIM * B_DIM];                 // p_gen per (t,b)

__device__ __forceinline__ float tanh_fast(float x) {
    float y;
    asm("tanh.approx.f32 %0, %1;" : "=f"(y) : "f"(x));
    return y;
}

__device__ __forceinline__ uint32_t f2tf32(float f) {
    uint32_t u;
    asm("cvt.rna.tf32.f32 %0, %1;" : "=r"(u) : "f"(f));
    return u;
}

// ---------------- TF32 tensor-core GEMM: C[M,N] = A[M,K] @ B[K,N] (+bias) ----------------
// BM=128, BN=128, BK=16, 256 threads (8 warps as 4m x 2n, warp tile 32x64).
// Requires M % 128 == 0, K % 16 == 0. N arbitrary (guarded).
#define GBM 128
#define GBN 128
#define GBK 16
#define AS_STRIDE 136   // frag read bank = (8k+m+c)%32 distinct -> conflict-free
#define BS_STRIDE 136   // frag read bank = (8k+n+c)%32 distinct -> conflict-free

__global__ __launch_bounds__(256) void gemm_tf32(
    const float* __restrict__ A, const float* __restrict__ Bm,
    const float* __restrict__ bias, float* __restrict__ C,
    int M, int N, int K)
{
    __shared__ __align__(16) float As[GBK][AS_STRIDE];
    __shared__ __align__(16) float Bs[GBK][BS_STRIDE];

    const int tid  = threadIdx.x;
    const int warp = tid >> 5;
    const int lane = tid & 31;
    const int wm = warp & 3;        // 0..3 -> 32-row slab
    const int wn = warp >> 2;       // 0..1 -> 64-col slab
    const int lk = lane & 3;        // thread's k group
    const int lm = lane >> 2;       // thread's row/col group (0..7)

    const int mBase = blockIdx.y * GBM;
    const int nBase = blockIdx.x * GBN;

    // producer mapping
    const int arow = tid & 127;           // A tile row
    const int akq  = (tid >> 7) * 8;      // A k offset: 0 or 8 (8 consecutive k)
    const int brow = tid >> 4;            // B tile k row 0..15
    const int bcol = (tid & 15) * 8;      // B col base (8 consecutive cols)

    float a_reg[8], b_reg[8];

    float acc[2][8][4];
#pragma unroll
    for (int i = 0; i < 2; i++)
#pragma unroll
        for (int j = 0; j < 8; j++)
#pragma unroll
            for (int q = 0; q < 4; q++) acc[i][j][q] = 0.f;

    const int nIters = K / GBK;

    // ---- fetch tile it=0 ----
    {
        const float* ap = &A[(size_t)(mBase + arow) * K + akq];
        float4 v0 = *(const float4*)(ap);
        float4 v1 = *(const float4*)(ap + 4);
        a_reg[0] = v0.x; a_reg[1] = v0.y; a_reg[2] = v0.z; a_reg[3] = v0.w;
        a_reg[4] = v1.x; a_reg[5] = v1.y; a_reg[6] = v1.z; a_reg[7] = v1.w;
        const float* bp = &Bm[(size_t)brow * N];
#pragma unroll
        for (int i = 0; i < 8; i++) {
            int c = nBase + bcol + i;
            b_reg[i] = (c < N) ? bp[c] : 0.f;
        }
    }
#pragma unroll
    for (int i = 0; i < 8; i++) As[akq + i][arow] = __uint_as_float(f2tf32(a_reg[i]));
#pragma unroll
    for (int i = 0; i < 8; i++) Bs[brow][bcol + i] = __uint_as_float(f2tf32(b_reg[i]));
    __syncthreads();

    for (int it = 0; it < nIters; ++it) {
        // prefetch next tile into registers
        if (it + 1 < nIters) {
            int k0 = (it + 1) * GBK;
            const float* ap = &A[(size_t)(mBase + arow) * K + k0 + akq];
            float4 v0 = *(const float4*)(ap);
            float4 v1 = *(const float4*)(ap + 4);
            a_reg[0] = v0.x; a_reg[1] = v0.y; a_reg[2] = v0.z; a_reg[3] = v0.w;
            a_reg[4] = v1.x; a_reg[5] = v1.y; a_reg[6] = v1.z; a_reg[7] = v1.w;
            const float* bp = &Bm[(size_t)(k0 + brow) * N];
#pragma unroll
            for (int i = 0; i < 8; i++) {
                int c = nBase + bcol + i;
                b_reg[i] = (c < N) ? bp[c] : 0.f;
            }
        }

        // compute on current smem tile: two k8 steps
#pragma unroll
        for (int ks = 0; ks < GBK; ks += 8) {
            uint32_t af[2][4];
#pragma unroll
            for (int mt = 0; mt < 2; mt++) {
                int r = wm * 32 + mt * 16 + lm;
                af[mt][0] = __float_as_uint(As[ks + lk    ][r    ]);
                af[mt][1] = __float_as_uint(As[ks + lk    ][r + 8]);
                af[mt][2] = __float_as_uint(As[ks + lk + 4][r    ]);
                af[mt][3] = __float_as_uint(As[ks + lk + 4][r + 8]);
            }
#pragma unroll
            for (int nt = 0; nt < 8; nt++) {
                int c = wn * 64 + nt * 8 + lm;
                // PTX m16n8k8 B frag: b0 at k=lane%4, b1 at k=lane%4+4
                uint32_t b0 = __float_as_uint(Bs[ks + lk    ][c]);
                uint32_t b1 = __float_as_uint(Bs[ks + lk + 4][c]);
#pragma unroll
                for (int mt = 0; mt < 2; mt++) {
                    asm volatile(
                        "mma.sync.aligned.m16n8k8.row.col.f32.tf32.tf32.f32 "
                        "{%0,%1,%2,%3}, {%4,%5,%6,%7}, {%8,%9}, {%0,%1,%2,%3};\n"
                        : "+f"(acc[mt][nt][0]), "+f"(acc[mt][nt][1]),
                          "+f"(acc[mt][nt][2]), "+f"(acc[mt][nt][3])
                        : "r"(af[mt][0]), "r"(af[mt][1]), "r"(af[mt][2]), "r"(af[mt][3]),
                          "r"(b0), "r"(b1));
                }
            }
        }
        __syncthreads();

        if (it + 1 < nIters) {
#pragma unroll
            for (int i = 0; i < 8; i++) As[akq + i][arow] = __uint_as_float(f2tf32(a_reg[i]));
#pragma unroll
            for (int i = 0; i < 8; i++) Bs[brow][bcol + i] = __uint_as_float(f2tf32(b_reg[i]));
            __syncthreads();
        }
    }

    // ---- epilogue: C frag layout m16n8.f32: (c0,c1)@row lm, cols 2lk,2lk+1; (c2,c3)@row lm+8
#pragma unroll
    for (int mt = 0; mt < 2; mt++) {
        int row0 = mBase + wm * 32 + mt * 16 + lm;
#pragma unroll
        for (int nt = 0; nt < 8; nt++) {
            int col = nBase + wn * 64 + nt * 8 + 2 * lk;
            float bi0 = 0.f, bi1 = 0.f;
            if (bias) {
                if (col     < N) bi0 = bias[col];
                if (col + 1 < N) bi1 = bias[col + 1];
            }
            if (col < N) {
                C[(size_t)row0 * N + col] = acc[mt][nt][0] + bi0;
                C[(size_t)(row0 + 8) * N + col] = acc[mt][nt][2] + bi0;
            }
            if (col + 1 < N) {
                C[(size_t)row0 * N + col + 1] = acc[mt][nt][1] + bi1;
                C[(size_t)(row0 + 8) * N + col + 1] = acc[mt][nt][3] + bi1;
            }
        }
    }
}

// ---------------- attention scores: attn[t,b,s] = sum_h tanh(dec+enc)*v ----------------
__global__ __launch_bounds__(256) void attn_score_kernel(const float* __restrict__ v_attn)
{
    int b = blockIdx.x >> 5;   // T/2 = 32 pairs
    int tp = blockIdx.x & 31;
    int w = threadIdx.x >> 5;
    int lane = threadIdx.x & 31;
    int t = tp * 2 + (w & 1);
    int sc = w >> 1;           // 0..3

    const float* drow = g_dec_proj + (size_t)(t * B_DIM + b) * H_DIM;
    float4 dreg[6], vreg[6];
#pragma unroll
    for (int i = 0; i < 6; i++) {
        dreg[i] = *reinterpret_cast<const float4*>(drow + i * 128 + lane * 4);
        vreg[i] = *reinterpret_cast<const float4*>(v_attn + i * 128 + lane * 4);
    }

    for (int s = sc * 64; s < sc * 64 + 64; s++) {
        const float* erow = g_enc_proj + (size_t)(s * B_DIM + b) * H_DIM;
        float acc = 0.f;
#pragma unroll
        for (int i = 0; i < 6; i++) {
            float4 e = *reinterpret_cast<const float4*>(erow + i * 128 + lane * 4);
            acc = fmaf(tanh_fast(dreg[i].x + e.x), vreg[i].x, acc);
            acc = fmaf(tanh_fast(dreg[i].y + e.y), vreg[i].y, acc);
            acc = fmaf(tanh_fast(dreg[i].z + e.z), vreg[i].z, acc);
            acc = fmaf(tanh_fast(dreg[i].w + e.w), vreg[i].w, acc);
        }
#pragma unroll
        for (int off = 16; off > 0; off >>= 1)
            acc += __shfl_xor_sync(0xffffffffu, acc, off);
        if (lane == 0)
            g_attn[(size_t)(t * B_DIM + b) * S_DIM + s] = acc;
    }
}

// ---------------- masked softmax over S (in place on g_attn) ----------------
__global__ __launch_bounds__(256) void softmax_s_kernel(const int* __restrict__ src_ids)
{
    int row = blockIdx.x;          // t*B + b
    int b = row & (B_DIM - 1);
    int s = threadIdx.x;
    float val = g_attn[(size_t)row * S_DIM + s];
    if (src_ids[s * B_DIM + b] == 0) val = -1e10f;

    __shared__ float red[256];
    red[s] = val;
    __syncthreads();
    for (int off = 128; off > 0; off >>= 1) {
        if (s < off) red[s] = fmaxf(red[s], red[s + off]);
        __syncthreads();
    }
    float m = red[0];
    __syncthreads();
    float e = __expf(val - m);
    red[s] = e;
    __syncthreads();
    for (int off = 128; off > 0; off >>= 1) {
        if (s < off) red[s] += red[s + off];
        __syncthreads();
    }
    g_attn[(size_t)row * S_DIM + s] = e / red[0];
}

// ---------------- ctx[t,b,h] = sum_s attn[t,b,s] * encoder_out[s,b,h] ----------------
__global__ __launch_bounds__(256) void ctx_kernel(const float* __restrict__ enc)
{
    int b = blockIdx.x >> 4;   // T/4 = 16 groups
    int tg = blockIdx.x & 15;
    int tid = threadIdx.x;

    __shared__ float p_sh[4][S_DIM];
    for (int i = tid; i < 4 * S_DIM; i += 256) {
        int tt = i >> 8;
        int ss = i & 255;
        p_sh[tt][ss] = g_attn[(size_t)((tg * 4 + tt) * B_DIM + b) * S_DIM + ss];
    }
    __syncthreads();

    float acc[4][3] = {};
    for (int s = 0; s < S_DIM; s++) {
        const float* erow = enc + (size_t)(s * B_DIM + b) * H_DIM;
        float e0 = erow[tid], e1 = erow[tid + 256], e2 = erow[tid + 512];
#pragma unroll
        for (int tt = 0; tt < 4; tt++) {
            float p = p_sh[tt][s];
            acc[tt][0] = fmaf(p, e0, acc[tt][0]);
            acc[tt][1] = fmaf(p, e1, acc[tt][1]);
            acc[tt][2] = fmaf(p, e2, acc[tt][2]);
        }
    }
#pragma unroll
    for (int tt = 0; tt < 4; tt++) {
        float* crow = g_ctx + (size_t)((tg * 4 + tt) * B_DIM + b) * H_DIM;
        crow[tid] = acc[tt][0];
        crow[tid + 256] = acc[tt][1];
        crow[tid + 512] = acc[tt][2];
    }
}

// ---------------- p_gen = sigmoid([dec;ctx;tgt] . W_pgen + b) ----------------
__global__ __launch_bounds__(256) void pgen_kernel(
    const float* __restrict__ ds, const float* __restrict__ tgt,
    const float* __restrict__ Wp, const float* __restrict__ bp)
{
    int row = blockIdx.x;     // t*B + b
    int tid = threadIdx.x;
    const float* dsr = ds + (size_t)row * H_DIM;
    const float* ctr = g_ctx + (size_t)row * H_DIM;
    const float* tgr = tgt + (size_t)row * H_DIM;
    float part = 0.f;
    for (int h = tid; h < H_DIM; h += 256)
        part += dsr[h] * Wp[h] + ctr[h] * Wp[H_DIM + h] + tgr[h] * Wp[2 * H_DIM + h];

    __shared__ float red[256];
    red[tid] = part;
    __syncthreads();
    for (int off = 128; off > 0; off >>= 1) {
        if (tid < off) red[tid] += red[tid + off];
        __syncthreads();
    }
    if (tid == 0) {
        float x = red[0] + bp[0];
        g_pg[row] = 1.f / (1.f + __expf(-x));
    }
}

// ---------------- softmax over V (in place on d_out), scaled by p_gen ----------------
__global__ __launch_bounds__(1024) void softmax_v_kernel(float* __restrict__ out)
{
    int row = blockIdx.x;     // t*B + b
    float* ptr = out + (size_t)row * V_DIM;
    int tid = threadIdx.x;

    float m = -3.4e38f, sum = 0.f;
    for (int v = tid; v < V_DIM; v += 1024) {
        float x = ptr[v];
        float nm = fmaxf(m, x);
        sum = sum * __expf(m - nm) + __expf(x - nm);
        m = nm;
    }
    __shared__ float sm[1024], ss[1024];
    sm[tid] = m;
    ss[tid] = sum;
    __syncthreads();
    for (int off = 512; off > 0; off >>= 1) {
        if (tid < off) {
            float m2 = sm[tid + off], s2 = ss[tid + off];
            float nm = fmaxf(sm[tid], m2);
            ss[tid] = ss[tid] * __expf(sm[tid] - nm) + s2 * __expf(m2 - nm);
            sm[tid] = nm;
        }
        __syncthreads();
    }
    float M = sm[0];
    float scale = g_pg[row] / ss[0];
    for (int v = tid; v < V_DIM; v += 1024)
        ptr[v] = __expf(ptr[v] - M) * scale;
}

// ---------------- scatter add: out[t,b,src_ids[s,b]] += attn*(1-pg) ----------------
__global__ __launch_bounds__(256) void scatter_kernel(
    const int* __restrict__ src_ids, float* __restrict__ out)
{
    int row = blockIdx.x;     // t*B + b
    int b = row & (B_DIM - 1);
    int s = threadIdx.x;
    float p = g_attn[(size_t)row * S_DIM + s];
    float w = 1.f - g_pg[row];
    int id = src_ids[s * B_DIM + b];
    if (id >= 0 && id < V_DIM)
        atomicAdd(out + (size_t)row * V_DIM + (size_t)id, p * w);
}

// ---------------- launcher ----------------
extern "C" void kernel_launch(void* const* d_in, const int* in_sizes, int n_in,
                              void* d_out, int out_size)
{
    const float* enc    = (const float*)d_in[0];   // (S,B,H)
    const float* ds     = (const float*)d_in[1];   // (T,B,H)
    const int*   srcids = (const int*)d_in[2];     // (S,B) int32 on device
    const float* tgt    = (const float*)d_in[3];   // (T,B,H)
    const float* W_attn = (const float*)d_in[4];   // (2H,H)
    const float* b_attn = (const float*)d_in[5];   // (H,)
    const float* v_attn = (const float*)d_in[6];   // (H,)
    // d_in[7] = b_v : cancels in softmax -> unused
    const float* W_pgen = (const float*)d_in[8];   // (3H,1)
    const float* b_pgen = (const float*)d_in[9];   // (1,)
    const float* W_gen  = (const float*)d_in[10];  // (H,V)
    const float* b_gen  = (const float*)d_in[11];  // (V,)
    float* out = (float*)d_out;

    float *dec_proj_p, *enc_proj_p;
    cudaGetSymbolAddress((void**)&dec_proj_p, g_dec_proj);
    cudaGetSymbolAddress((void**)&enc_proj_p, g_enc_proj);

    // 1) dec_proj = decoder_state @ W_attn[:H]           (512 x 768, K=768)
    gemm_tf32<<<dim3(768 / GBN, (T_DIM * B_DIM) / GBM), 256>>>(
        ds, W_attn, nullptr, dec_proj_p, T_DIM * B_DIM, H_DIM, H_DIM);

    // 2) enc_proj = encoder_out @ W_attn[H:] + b_attn    (2048 x 768, K=768)
    gemm_tf32<<<dim3(768 / GBN, (S_DIM * B_DIM) / GBM), 256>>>(
        enc, W_attn + (size_t)H_DIM * H_DIM, b_attn, enc_proj_p,
        S_DIM * B_DIM, H_DIM, H_DIM);

    // 3) additive attention scores
    attn_score_kernel<<<B_DIM * (T_DIM / 2), 256>>>(v_attn);

    // 4) masked softmax over S
    softmax_s_kernel<<<T_DIM * B_DIM, 256>>>(srcids);

    // 5) context vectors
    ctx_kernel<<<B_DIM * (T_DIM / 4), 256>>>(enc);

    // 6) p_gen
    pgen_kernel<<<T_DIM * B_DIM, 256>>>(ds, tgt, W_pgen, b_pgen);

    // 7) vocab logits straight into d_out                (512 x 50257, K=768)
    gemm_tf32<<<dim3((V_DIM + GBN - 1) / GBN, (T_DIM * B_DIM) / GBM), 256>>>(
        ds, W_gen, b_gen, out, T_DIM * B_DIM, V_DIM, H_DIM);

    // 8) softmax over V, scaled by p_gen (in place)
    softmax_v_kernel<<<T_DIM * B_DIM, 1024>>>(out);

    // 9) scatter-add copy distribution
    scatter_kernel<<<T_DIM * B_DIM, 256>>>(srcids, out);
}

// round 6
// speedup vs baseline: 3.0033x; 1.5557x over previous
#include <cuda_runtime.h>
#include <cuda_fp16.h>
#include <stdint.h>
#include <math.h>

#define S_DIM 256
#define T_DIM 64
#define B_DIM 8
#define H_DIM 768
#define V_DIM 50257
#define K2_TOT (H_DIM / 2)     // 384 packed k-pairs

// ---------------- device scratch (no allocs allowed) ----------------
__device__ float g_dec_proj[T_DIM * B_DIM * H_DIM];   // (T,B,H)
__device__ float g_enc_proj[S_DIM * B_DIM * H_DIM];   // (S,B,H)
__device__ float g_attn[T_DIM * B_DIM * S_DIM];       // (T,B,S) scores -> probs in place
__device__ float g_ctx[T_DIM * B_DIM * H_DIM];        // (T,B,H)
__device__ float g_pg[T_DIM * B_DIM];                 // p_gen per (t,b)
__device__ uint32_t g_Wp[(size_t)K2_TOT * V_DIM];     // W_gen fp16, [k2][n], k-pair packed (77MB)
__device__ uint32_t g_Ap[(size_t)K2_TOT * (T_DIM * B_DIM)]; // decoder_state fp16 [k2][m]

__device__ __forceinline__ float tanh_fast(float x) {
    float y;
    asm("tanh.approx.f32 %0, %1;" : "=f"(y) : "f"(x));
    return y;
}

__device__ __forceinline__ uint32_t f2tf32(float f) {
    uint32_t u;
    asm("cvt.rna.tf32.f32 %0, %1;" : "=r"(u) : "f"(f));
    return u;
}

// ---------------- fp16 pack conversions ----------------
// Wp[k2][n] = half2(W[2k2][n], W[2k2+1][n])
__global__ __launch_bounds__(256) void conv_w_kernel(const float* __restrict__ W,
                                                     uint32_t* __restrict__ Wp)
{
    int n = blockIdx.x * 256 + threadIdx.x;
    int k2 = blockIdx.y;
    if (n >= V_DIM) return;
    float lo = W[(size_t)(2 * k2) * V_DIM + n];
    float hi = W[(size_t)(2 * k2 + 1) * V_DIM + n];
    __half2 h = __floats2half2_rn(lo, hi);
    Wp[(size_t)k2 * V_DIM + n] = *reinterpret_cast<uint32_t*>(&h);
}

// Ap[k2][m] = half2(ds[m][2k2], ds[m][2k2+1])
__global__ __launch_bounds__(256) void conv_a_kernel(const float* __restrict__ ds,
                                                     uint32_t* __restrict__ Ap)
{
    int m = blockIdx.x * 256 + threadIdx.x;   // 0..511
    int k2 = blockIdx.y;                      // 0..383
    float lo = ds[(size_t)m * H_DIM + 2 * k2];
    float hi = ds[(size_t)m * H_DIM + 2 * k2 + 1];
    __half2 h = __floats2half2_rn(lo, hi);
    Ap[(size_t)k2 * (T_DIM * B_DIM) + m] = *reinterpret_cast<uint32_t*>(&h);
}

// ---------------- fp16 tensor-core GEMM (vocab): C[M,N] = A @ B (+bias) ----------------
// Inputs pre-packed k2-major: Ap[k2][M], Bp[k2][N] (u32 = half2 of k-pair).
// BM=128, BN=128, BK=32 (16 k2), 256 threads, 8 warps (4m x 2n), warp tile 32x64.
#define FBK2 16
#define FSTR 136   // frag read bank = (8*lk + lm + c) % 32 -> conflict-free; stores 0..31 -> perfect

__global__ __launch_bounds__(256) void gemm_f16(
    const uint32_t* __restrict__ Ap, const uint32_t* __restrict__ Bp,
    const float* __restrict__ bias, float* __restrict__ C,
    int M, int N)
{
    __shared__ __align__(16) uint32_t As[FBK2][FSTR];
    __shared__ __align__(16) uint32_t Bs[FBK2][FSTR];

    const int tid  = threadIdx.x;
    const int warp = tid >> 5;
    const int lane = tid & 31;
    const int wm = warp & 3;
    const int wn = warp >> 2;
    const int lk = lane & 3;
    const int lm = lane >> 2;

    const int mBase = blockIdx.x * 128;   // m fastest -> 4 m-tiles share W slice in L2
    const int nBase = blockIdx.y * 128;

    const int pcol = tid & 127;           // producer column (m or n)
    const int prow0 = tid >> 7;           // 0 or 1; rows prow0, prow0+2, ... (8 rows each)

    uint32_t a_reg[8], b_reg[8];
    float acc[2][8][4];
#pragma unroll
    for (int i = 0; i < 2; i++)
#pragma unroll
        for (int j = 0; j < 8; j++)
#pragma unroll
            for (int q = 0; q < 4; q++) acc[i][j][q] = 0.f;

    const int nIters = K2_TOT / FBK2;     // 24

    // fetch tile 0
#pragma unroll
    for (int i = 0; i < 8; i++) {
        int r = prow0 + i * 2;
        a_reg[i] = Ap[(size_t)r * M + mBase + pcol];
        int c = nBase + pcol;
        b_reg[i] = (c < N) ? Bp[(size_t)r * N + c] : 0u;
    }
#pragma unroll
    for (int i = 0; i < 8; i++) { As[prow0 + i * 2][pcol] = a_reg[i]; Bs[prow0 + i * 2][pcol] = b_reg[i]; }
    __syncthreads();

    for (int it = 0; it < nIters; ++it) {
        if (it + 1 < nIters) {
            int k2b = (it + 1) * FBK2;
#pragma unroll
            for (int i = 0; i < 8; i++) {
                int r = k2b + prow0 + i * 2;
                a_reg[i] = Ap[(size_t)r * M + mBase + pcol];
                int c = nBase + pcol;
                b_reg[i] = (c < N) ? Bp[(size_t)r * N + c] : 0u;
            }
        }

#pragma unroll
        for (int ks = 0; ks < 2; ks++) {       // two k16 steps
            const int kq = ks * 8;
            uint32_t af[2][4];
#pragma unroll
            for (int mt = 0; mt < 2; mt++) {
                int r = wm * 32 + mt * 16 + lm;
                af[mt][0] = As[kq + lk    ][r    ];
                af[mt][1] = As[kq + lk    ][r + 8];
                af[mt][2] = As[kq + lk + 4][r    ];
                af[mt][3] = As[kq + lk + 4][r + 8];
            }
#pragma unroll
            for (int nt = 0; nt < 8; nt++) {
                int c = wn * 64 + nt * 8 + lm;
                uint32_t b0 = Bs[kq + lk    ][c];
                uint32_t b1 = Bs[kq + lk + 4][c];
#pragma unroll
                for (int mt = 0; mt < 2; mt++) {
                    asm volatile(
                        "mma.sync.aligned.m16n8k16.row.col.f32.f16.f16.f32 "
                        "{%0,%1,%2,%3}, {%4,%5,%6,%7}, {%8,%9}, {%0,%1,%2,%3};\n"
                        : "+f"(acc[mt][nt][0]), "+f"(acc[mt][nt][1]),
                          "+f"(acc[mt][nt][2]), "+f"(acc[mt][nt][3])
                        : "r"(af[mt][0]), "r"(af[mt][1]), "r"(af[mt][2]), "r"(af[mt][3]),
                          "r"(b0), "r"(b1));
                }
            }
        }
        __syncthreads();

        if (it + 1 < nIters) {
#pragma unroll
            for (int i = 0; i < 8; i++) { As[prow0 + i * 2][pcol] = a_reg[i]; Bs[prow0 + i * 2][pcol] = b_reg[i]; }
            __syncthreads();
        }
    }

#pragma unroll
    for (int mt = 0; mt < 2; mt++) {
        int row0 = mBase + wm * 32 + mt * 16 + lm;
#pragma unroll
        for (int nt = 0; nt < 8; nt++) {
            int col = nBase + wn * 64 + nt * 8 + 2 * lk;
            float bi0 = 0.f, bi1 = 0.f;
            if (col     < N) bi0 = bias[col];
            if (col + 1 < N) bi1 = bias[col + 1];
            if (col < N) {
                C[(size_t)row0 * N + col] = acc[mt][nt][0] + bi0;
                C[(size_t)(row0 + 8) * N + col] = acc[mt][nt][2] + bi0;
            }
            if (col + 1 < N) {
                C[(size_t)row0 * N + col + 1] = acc[mt][nt][1] + bi1;
                C[(size_t)(row0 + 8) * N + col + 1] = acc[mt][nt][3] + bi1;
            }
        }
    }
}

// ---------------- TF32 tensor-core GEMM (attention projections) ----------------
#define GBM 128
#define GBN 128
#define GBK 16
#define AS_STRIDE 136
#define BS_STRIDE 136

__global__ __launch_bounds__(256) void gemm_tf32(
    const float* __restrict__ A, const float* __restrict__ Bm,
    const float* __restrict__ bias, float* __restrict__ C,
    int M, int N, int K)
{
    __shared__ __align__(16) float As[GBK][AS_STRIDE];
    __shared__ __align__(16) float Bs[GBK][BS_STRIDE];

    const int tid  = threadIdx.x;
    const int warp = tid >> 5;
    const int lane = tid & 31;
    const int wm = warp & 3;
    const int wn = warp >> 2;
    const int lk = lane & 3;
    const int lm = lane >> 2;

    const int mBase = blockIdx.y * GBM;
    const int nBase = blockIdx.x * GBN;

    const int arow = tid & 127;
    const int akq  = (tid >> 7) * 8;
    const int brow = tid >> 4;
    const int bcol = (tid & 15) * 8;

    float a_reg[8], b_reg[8];
    float acc[2][8][4];
#pragma unroll
    for (int i = 0; i < 2; i++)
#pragma unroll
        for (int j = 0; j < 8; j++)
#pragma unroll
            for (int q = 0; q < 4; q++) acc[i][j][q] = 0.f;

    const int nIters = K / GBK;

    {
        const float* ap = &A[(size_t)(mBase + arow) * K + akq];
        float4 v0 = *(const float4*)(ap);
        float4 v1 = *(const float4*)(ap + 4);
        a_reg[0] = v0.x; a_reg[1] = v0.y; a_reg[2] = v0.z; a_reg[3] = v0.w;
        a_reg[4] = v1.x; a_reg[5] = v1.y; a_reg[6] = v1.z; a_reg[7] = v1.w;
        const float* bp = &Bm[(size_t)brow * N];
#pragma unroll
        for (int i = 0; i < 8; i++) {
            int c = nBase + bcol + i;
            b_reg[i] = (c < N) ? bp[c] : 0.f;
        }
    }
#pragma unroll
    for (int i = 0; i < 8; i++) As[akq + i][arow] = __uint_as_float(f2tf32(a_reg[i]));
#pragma unroll
    for (int i = 0; i < 8; i++) Bs[brow][bcol + i] = __uint_as_float(f2tf32(b_reg[i]));
    __syncthreads();

    for (int it = 0; it < nIters; ++it) {
        if (it + 1 < nIters) {
            int k0 = (it + 1) * GBK;
            const float* ap = &A[(size_t)(mBase + arow) * K + k0 + akq];
            float4 v0 = *(const float4*)(ap);
            float4 v1 = *(const float4*)(ap + 4);
            a_reg[0] = v0.x; a_reg[1] = v0.y; a_reg[2] = v0.z; a_reg[3] = v0.w;
            a_reg[4] = v1.x; a_reg[5] = v1.y; a_reg[6] = v1.z; a_reg[7] = v1.w;
            const float* bp = &Bm[(size_t)(k0 + brow) * N];
#pragma unroll
            for (int i = 0; i < 8; i++) {
                int c = nBase + bcol + i;
                b_reg[i] = (c < N) ? bp[c] : 0.f;
            }
        }

#pragma unroll
        for (int ks = 0; ks < GBK; ks += 8) {
            uint32_t af[2][4];
#pragma unroll
            for (int mt = 0; mt < 2; mt++) {
                int r = wm * 32 + mt * 16 + lm;
                af[mt][0] = __float_as_uint(As[ks + lk    ][r    ]);
                af[mt][1] = __float_as_uint(As[ks + lk    ][r + 8]);
                af[mt][2] = __float_as_uint(As[ks + lk + 4][r    ]);
                af[mt][3] = __float_as_uint(As[ks + lk + 4][r + 8]);
            }
#pragma unroll
            for (int nt = 0; nt < 8; nt++) {
                int c = wn * 64 + nt * 8 + lm;
                uint32_t b0 = __float_as_uint(Bs[ks + lk    ][c]);
                uint32_t b1 = __float_as_uint(Bs[ks + lk + 4][c]);
#pragma unroll
                for (int mt = 0; mt < 2; mt++) {
                    asm volatile(
                        "mma.sync.aligned.m16n8k8.row.col.f32.tf32.tf32.f32 "
                        "{%0,%1,%2,%3}, {%4,%5,%6,%7}, {%8,%9}, {%0,%1,%2,%3};\n"
                        : "+f"(acc[mt][nt][0]), "+f"(acc[mt][nt][1]),
                          "+f"(acc[mt][nt][2]), "+f"(acc[mt][nt][3])
                        : "r"(af[mt][0]), "r"(af[mt][1]), "r"(af[mt][2]), "r"(af[mt][3]),
                          "r"(b0), "r"(b1));
                }
            }
        }
        __syncthreads();

        if (it + 1 < nIters) {
#pragma unroll
            for (int i = 0; i < 8; i++) As[akq + i][arow] = __uint_as_float(f2tf32(a_reg[i]));
#pragma unroll
            for (int i = 0; i < 8; i++) Bs[brow][bcol + i] = __uint_as_float(f2tf32(b_reg[i]));
            __syncthreads();
        }
    }

#pragma unroll
    for (int mt = 0; mt < 2; mt++) {
        int row0 = mBase + wm * 32 + mt * 16 + lm;
#pragma unroll
        for (int nt = 0; nt < 8; nt++) {
            int col = nBase + wn * 64 + nt * 8 + 2 * lk;
            float bi0 = 0.f, bi1 = 0.f;
            if (bias) {
                if (col     < N) bi0 = bias[col];
                if (col + 1 < N) bi1 = bias[col + 1];
            }
            if (col < N) {
                C[(size_t)row0 * N + col] = acc[mt][nt][0] + bi0;
                C[(size_t)(row0 + 8) * N + col] = acc[mt][nt][2] + bi0;
            }
            if (col + 1 < N) {
                C[(size_t)row0 * N + col + 1] = acc[mt][nt][1] + bi1;
                C[(size_t)(row0 + 8) * N + col + 1] = acc[mt][nt][3] + bi1;
            }
        }
    }
}

// ---------------- attention scores: attn[t,b,s] = sum_h tanh(dec+enc)*v ----------------
__global__ __launch_bounds__(256) void attn_score_kernel(const float* __restrict__ v_attn)
{
    int b = blockIdx.x >> 5;
    int tp = blockIdx.x & 31;
    int w = threadIdx.x >> 5;
    int lane = threadIdx.x & 31;
    int t = tp * 2 + (w & 1);
    int sc = w >> 1;

    const float* drow = g_dec_proj + (size_t)(t * B_DIM + b) * H_DIM;
    float4 dreg[6], vreg[6];
#pragma unroll
    for (int i = 0; i < 6; i++) {
        dreg[i] = *reinterpret_cast<const float4*>(drow + i * 128 + lane * 4);
        vreg[i] = *reinterpret_cast<const float4*>(v_attn + i * 128 + lane * 4);
    }

    for (int s = sc * 64; s < sc * 64 + 64; s++) {
        const float* erow = g_enc_proj + (size_t)(s * B_DIM + b) * H_DIM;
        float acc = 0.f;
#pragma unroll
        for (int i = 0; i < 6; i++) {
            float4 e = *reinterpret_cast<const float4*>(erow + i * 128 + lane * 4);
            acc = fmaf(tanh_fast(dreg[i].x + e.x), vreg[i].x, acc);
            acc = fmaf(tanh_fast(dreg[i].y + e.y), vreg[i].y, acc);
            acc = fmaf(tanh_fast(dreg[i].z + e.z), vreg[i].z, acc);
            acc = fmaf(tanh_fast(dreg[i].w + e.w), vreg[i].w, acc);
        }
#pragma unroll
        for (int off = 16; off > 0; off >>= 1)
            acc += __shfl_xor_sync(0xffffffffu, acc, off);
        if (lane == 0)
            g_attn[(size_t)(t * B_DIM + b) * S_DIM + s] = acc;
    }
}

// ---------------- masked softmax over S (in place on g_attn) ----------------
__global__ __launch_bounds__(256) void softmax_s_kernel(const int* __restrict__ src_ids)
{
    int row = blockIdx.x;
    int b = row & (B_DIM - 1);
    int s = threadIdx.x;
    float val = g_attn[(size_t)row * S_DIM + s];
    if (src_ids[s * B_DIM + b] == 0) val = -1e10f;

    __shared__ float red[256];
    red[s] = val;
    __syncthreads();
    for (int off = 128; off > 0; off >>= 1) {
        if (s < off) red[s] = fmaxf(red[s], red[s + off]);
        __syncthreads();
    }
    float m = red[0];
    __syncthreads();
    float e = __expf(val - m);
    red[s] = e;
    __syncthreads();
    for (int off = 128; off > 0; off >>= 1) {
        if (s < off) red[s] += red[s + off];
        __syncthreads();
    }
    g_attn[(size_t)row * S_DIM + s] = e / red[0];
}

// ---------------- ctx[t,b,h] = sum_s attn[t,b,s] * encoder_out[s,b,h] ----------------
__global__ __launch_bounds__(256) void ctx_kernel(const float* __restrict__ enc)
{
    int b = blockIdx.x >> 4;
    int tg = blockIdx.x & 15;
    int tid = threadIdx.x;

    __shared__ float p_sh[4][S_DIM];
    for (int i = tid; i < 4 * S_DIM; i += 256) {
        int tt = i >> 8;
        int ss = i & 255;
        p_sh[tt][ss] = g_attn[(size_t)((tg * 4 + tt) * B_DIM + b) * S_DIM + ss];
    }
    __syncthreads();

    float acc[4][3] = {};
    for (int s = 0; s < S_DIM; s++) {
        const float* erow = enc + (size_t)(s * B_DIM + b) * H_DIM;
        float e0 = erow[tid], e1 = erow[tid + 256], e2 = erow[tid + 512];
#pragma unroll
        for (int tt = 0; tt < 4; tt++) {
            float p = p_sh[tt][s];
            acc[tt][0] = fmaf(p, e0, acc[tt][0]);
            acc[tt][1] = fmaf(p, e1, acc[tt][1]);
            acc[tt][2] = fmaf(p, e2, acc[tt][2]);
        }
    }
#pragma unroll
    for (int tt = 0; tt < 4; tt++) {
        float* crow = g_ctx + (size_t)((tg * 4 + tt) * B_DIM + b) * H_DIM;
        crow[tid] = acc[tt][0];
        crow[tid + 256] = acc[tt][1];
        crow[tid + 512] = acc[tt][2];
    }
}

// ---------------- p_gen = sigmoid([dec;ctx;tgt] . W_pgen + b) ----------------
__global__ __launch_bounds__(256) void pgen_kernel(
    const float* __restrict__ ds, const float* __restrict__ tgt,
    const float* __restrict__ Wp, const float* __restrict__ bp)
{
    int row = blockIdx.x;
    int tid = threadIdx.x;
    const float* dsr = ds + (size_t)row * H_DIM;
    const float* ctr = g_ctx + (size_t)row * H_DIM;
    const float* tgr = tgt + (size_t)row * H_DIM;
    float part = 0.f;
    for (int h = tid; h < H_DIM; h += 256)
        part += dsr[h] * Wp[h] + ctr[h] * Wp[H_DIM + h] + tgr[h] * Wp[2 * H_DIM + h];

    __shared__ float red[256];
    red[tid] = part;
    __syncthreads();
    for (int off = 128; off > 0; off >>= 1) {
        if (tid < off) red[tid] += red[tid + off];
        __syncthreads();
    }
    if (tid == 0) {
        float x = red[0] + bp[0];
        g_pg[row] = 1.f / (1.f + __expf(-x));
    }
}

// ---------------- softmax over V (in place on d_out), scaled by p_gen ----------------
__global__ __launch_bounds__(1024) void softmax_v_kernel(float* __restrict__ out)
{
    int row = blockIdx.x;
    float* ptr = out + (size_t)row * V_DIM;
    int tid = threadIdx.x;

    float m = -3.4e38f, sum = 0.f;
    for (int v = tid; v < V_DIM; v += 1024) {
        float x = ptr[v];
        float nm = fmaxf(m, x);
        sum = sum * __expf(m - nm) + __expf(x - nm);
        m = nm;
    }
    __shared__ float sm[1024], ss[1024];
    sm[tid] = m;
    ss[tid] = sum;
    __syncthreads();
    for (int off = 512; off > 0; off >>= 1) {
        if (tid < off) {
            float m2 = sm[tid + off], s2 = ss[tid + off];
            float nm = fmaxf(sm[tid], m2);
            ss[tid] = ss[tid] * __expf(sm[tid] - nm) + s2 * __expf(m2 - nm);
            sm[tid] = nm;
        }
        __syncthreads();
    }
    float M = sm[0];
    float scale = g_pg[row] / ss[0];
    for (int v = tid; v < V_DIM; v += 1024)
        ptr[v] = __expf(ptr[v] - M) * scale;
}

// ---------------- scatter add: out[t,b,src_ids[s,b]] += attn*(1-pg) ----------------
__global__ __launch_bounds__(256) void scatter_kernel(
    const int* __restrict__ src_ids, float* __restrict__ out)
{
    int row = blockIdx.x;
    int b = row & (B_DIM - 1);
    int s = threadIdx.x;
    float p = g_attn[(size_t)row * S_DIM + s];
    float w = 1.f - g_pg[row];
    int id = src_ids[s * B_DIM + b];
    if (id >= 0 && id < V_DIM)
        atomicAdd(out + (size_t)row * V_DIM + (size_t)id, p * w);
}

// ---------------- launcher ----------------
extern "C" void kernel_launch(void* const* d_in, const int* in_sizes, int n_in,
                              void* d_out, int out_size)
{
    const float* enc    = (const float*)d_in[0];   // (S,B,H)
    const float* ds     = (const float*)d_in[1];   // (T,B,H)
    const int*   srcids = (const int*)d_in[2];     // (S,B) int32 on device
    const float* tgt    = (const float*)d_in[3];   // (T,B,H)
    const float* W_attn = (const float*)d_in[4];   // (2H,H)
    const float* b_attn = (const float*)d_in[5];   // (H,)
    const float* v_attn = (const float*)d_in[6];   // (H,)
    // d_in[7] = b_v : cancels in softmax -> unused
    const float* W_pgen = (const float*)d_in[8];   // (3H,1)
    const float* b_pgen = (const float*)d_in[9];   // (1,)
    const float* W_gen  = (const float*)d_in[10];  // (H,V)
    const float* b_gen  = (const float*)d_in[11];  // (V,)
    float* out = (float*)d_out;

    float *dec_proj_p, *enc_proj_p;
    uint32_t *wp_p, *ap_p;
    cudaGetSymbolAddress((void**)&dec_proj_p, g_dec_proj);
    cudaGetSymbolAddress((void**)&enc_proj_p, g_enc_proj);
    cudaGetSymbolAddress((void**)&wp_p, g_Wp);
    cudaGetSymbolAddress((void**)&ap_p, g_Ap);

    // 0) fp16 pack conversions for the vocab GEMM
    conv_w_kernel<<<dim3((V_DIM + 255) / 256, K2_TOT), 256>>>(W_gen, wp_p);
    conv_a_kernel<<<dim3((T_DIM * B_DIM) / 256, K2_TOT), 256>>>(ds, ap_p);

    // 1) dec_proj = decoder_state @ W_attn[:H]           (512 x 768, K=768)
    gemm_tf32<<<dim3(768 / GBN, (T_DIM * B_DIM) / GBM), 256>>>(
        ds, W_attn, nullptr, dec_proj_p, T_DIM * B_DIM, H_DIM, H_DIM);

    // 2) enc_proj = encoder_out @ W_attn[H:] + b_attn    (2048 x 768, K=768)
    gemm_tf32<<<dim3(768 / GBN, (S_DIM * B_DIM) / GBM), 256>>>(
        enc, W_attn + (size_t)H_DIM * H_DIM, b_attn, enc_proj_p,
        S_DIM * B_DIM, H_DIM, H_DIM);

    // 3) additive attention scores
    attn_score_kernel<<<B_DIM * (T_DIM / 2), 256>>>(v_attn);

    // 4) masked softmax over S
    softmax_s_kernel<<<T_DIM * B_DIM, 256>>>(srcids);

    // 5) context vectors
    ctx_kernel<<<B_DIM * (T_DIM / 4), 256>>>(enc);

    // 6) p_gen
    pgen_kernel<<<T_DIM * B_DIM, 256>>>(ds, tgt, W_pgen, b_pgen);

    // 7) vocab logits straight into d_out  (512 x 50257, K=768), fp16 tensor cores
    gemm_f16<<<dim3((T_DIM * B_DIM) / 128, (V_DIM + 127) / 128), 256>>>(
        ap_p, wp_p, b_gen, out, T_DIM * B_DIM, V_DIM);

    // 8) softmax over V, scaled by p_gen (in place)
    softmax_v_kernel<<<T_DIM * B_DIM, 1024>>>(out);

    // 9) scatter-add copy distribution
    scatter_kernel<<<T_DIM * B_DIM, 256>>>(srcids, out);
}